// round 10
// baseline (speedup 1.0000x reference)
#include <cuda_runtime.h>
#include <cstdint>

#define HH 50
#define DD 64
#define NT 128

__global__ void zero_tail_kernel(float* __restrict__ out, int off) {
    if (threadIdx.x == 0) { out[off] = 0.f; out[off + 1] = 0.f; }
}

__global__ void __launch_bounds__(NT) fused_kernel(
    const int* __restrict__ user1, const int* __restrict__ item1,
    const int* __restrict__ user2, const int* __restrict__ item2,
    const int* __restrict__ u_his, const int* __restrict__ u_pos, const int* __restrict__ u_mask,
    const int* __restrict__ i_his, const int* __restrict__ i_pos, const int* __restrict__ i_mask,
    const float* __restrict__ user1_emb, const float* __restrict__ item1_emb,
    const float* __restrict__ user1_bias, const float* __restrict__ item1_bias,
    const float* __restrict__ u_pos_emb,
    const float* __restrict__ user2_emb, const float* __restrict__ item2_emb,
    const float* __restrict__ user2_bias, const float* __restrict__ item2_bias,
    const float* __restrict__ i_pos_emb,
    const float* __restrict__ attn_u_W, const float* __restrict__ attn_u_b,
    const float* __restrict__ attn_i_W, const float* __restrict__ attn_i_b,
    float* __restrict__ out, int B)
{
    __shared__ int   sih[HH], sip[HH];
    __shared__ float smk[HH];
    __shared__ __align__(16) float part[4][2][DD];  // per-warp unnormalized d partials
    __shared__ float sZ[4][2];                      // per-warp Z partials
    __shared__ float sred[4];

    const int tid   = threadIdx.x;
    const int b     = blockIdx.x;
    const int phase = blockIdx.y;            // 0 = u-branch keys, 1 = i-branch keys
    const int warp  = tid >> 5, lane = tid & 31;
    const int g     = tid >> 4, l16  = tid & 15;

    const int u1 = user1[b], i1 = item1[b], u2 = user2[b], i2 = item2[b];

    const int*   his  = phase ? i_his  : u_his;
    const int*   pos  = phase ? i_pos  : u_pos;
    const int*   msk  = phase ? i_mask : u_mask;
    const float* emb  = phase ? user2_emb : item1_emb;
    const float* pemb = phase ? i_pos_emb : u_pos_emb;
    const float* W    = phase ? attn_i_W  : attn_u_W;
    const float  batt = phase ? attn_i_b[0] : attn_u_b[0];

    // ---- stage indices/masks in smem (3 coalesced loads) ----
    if (tid < HH) {
        sih[tid] = __ldg(his + b * HH + tid);
        sip[tid] = __ldg(pos + b * HH + tid);
        smk[tid] = (__ldg(msk + b * HH + tid) != 0) ? 1.f : 0.f;
    }

    // ---- every warp computes cq for BOTH queries (redundant, broadcast loads) ----
    const float* QA = phase ? user2_emb + (size_t)u1 * DD : item1_emb + (size_t)i1 * DD;
    const float* QB = phase ? user1_emb + (size_t)u1 * DD : item2_emb + (size_t)i1 * DD;
    float wq0 = __ldg(W + lane), wq1 = __ldg(W + lane + 32);
    float cqA = __ldg(QA + lane) * wq0 + __ldg(QA + lane + 32) * wq1;
    float cqB = __ldg(QB + lane) * wq0 + __ldg(QB + lane + 32) * wq1;
    #pragma unroll
    for (int o = 16; o; o >>= 1) {
        cqA += __shfl_xor_sync(0xffffffffu, cqA, o);
        cqB += __shfl_xor_sync(0xffffffffu, cqB, o);
    }
    cqA += batt; cqB += batt;

    const float4 wk = __ldg((const float4*)(W + DD) + l16);
    __syncthreads();

    // ---- gather + consume each key row immediately (unnormalized softmax) ----
    float4 accA = make_float4(0.f, 0.f, 0.f, 0.f);
    float4 accB = make_float4(0.f, 0.f, 0.f, 0.f);
    float ZA = 0.f, ZB = 0.f, regacc = 0.f;

    #pragma unroll
    for (int p = 0; p < 7; ++p) {
        const int h = p * 8 + g;
        if (h < HH) {
            int   ih = sih[h];
            int   ip = sip[h];
            float m  = smk[h];
            float4 e  = __ldg((const float4*)emb  + (size_t)ih * 16 + l16);
            float4 pp = __ldg((const float4*)pemb + (size_t)ip * 16 + l16);
            regacc += m * (e.x * e.x + e.y * e.y + e.z * e.z + e.w * e.w);
            float4 k;
            k.x = (e.x + pp.x) * m; k.y = (e.y + pp.y) * m;
            k.z = (e.z + pp.z) * m; k.w = (e.w + pp.w) * m;
            // key-side dot, butterfly so all 16 lanes get kd
            float kd = k.x * wk.x + k.y * wk.y + k.z * wk.z + k.w * wk.w;
            #pragma unroll
            for (int o = 8; o; o >>= 1) kd += __shfl_xor_sync(0xffffffffu, kd, o, 16);
            // scores in [-1,1] -> exp safe without max subtraction
            float eA = __expf(tanhf(cqA + kd));
            float eB = __expf(tanhf(cqB + kd));
            ZA += eA; ZB += eB;
            accA.x += eA * k.x; accA.y += eA * k.y; accA.z += eA * k.z; accA.w += eA * k.w;
            accB.x += eB * k.x; accB.y += eB * k.y; accB.z += eB * k.z; accB.w += eB * k.w;
        }
    }

    // ---- combine the two 16-lane groups in each warp; store warp partials ----
    accA.x += __shfl_down_sync(0xffffffffu, accA.x, 16);
    accA.y += __shfl_down_sync(0xffffffffu, accA.y, 16);
    accA.z += __shfl_down_sync(0xffffffffu, accA.z, 16);
    accA.w += __shfl_down_sync(0xffffffffu, accA.w, 16);
    accB.x += __shfl_down_sync(0xffffffffu, accB.x, 16);
    accB.y += __shfl_down_sync(0xffffffffu, accB.y, 16);
    accB.z += __shfl_down_sync(0xffffffffu, accB.z, 16);
    accB.w += __shfl_down_sync(0xffffffffu, accB.w, 16);
    ZA += __shfl_down_sync(0xffffffffu, ZA, 16);
    ZB += __shfl_down_sync(0xffffffffu, ZB, 16);
    if (lane < 16) {
        ((float4*)part[warp][0])[l16] = accA;
        ((float4*)part[warp][1])[l16] = accB;
        if (lane == 0) { sZ[warp][0] = ZA; sZ[warp][1] = ZB; }
    }
    __syncthreads();

    // ---- fold 4 warp partials, normalize, final logits + reg-loss norms ----
    if (warp < 2) {
        const int q = warp;
        float d0 = 0.f, d1 = 0.f;
        #pragma unroll
        for (int w = 0; w < 4; ++w) {
            float2 t = *(const float2*)&part[w][q][2 * lane];
            d0 += t.x; d1 += t.y;
        }
        float Z = sZ[0][q] + sZ[1][q] + sZ[2][q] + sZ[3][q];
        float invZ = 1.f / Z;
        d0 *= invZ; d1 *= invZ;

        const float *Av, *Bv; float bias; int ooff;
        if (phase == 0) {
            if (q == 0) {      // logits_us
                Av = item1_emb + (size_t)i1 * DD; Bv = user1_emb + (size_t)u1 * DD;
                bias = user1_bias[u1] + item1_bias[i1]; ooff = b;
            } else {           // logits_ur
                Av = item1_emb + (size_t)i2 * DD; Bv = user1_emb + (size_t)u2 * DD;
                bias = user1_bias[u2] + item1_bias[i2]; ooff = 2 * B + b;
            }
        } else {
            if (q == 0) {      // logits_ir
                Av = item2_emb + (size_t)i1 * DD; Bv = user2_emb + (size_t)u1 * DD;
                bias = user2_bias[u1] + item2_bias[i1]; ooff = B + b;
            } else {           // logits_is
                Av = item2_emb + (size_t)i2 * DD; Bv = user2_emb + (size_t)u2 * DD;
                bias = user2_bias[u2] + item2_bias[i2]; ooff = 3 * B + b;
            }
        }
        float2 av = __ldg((const float2*)Av + lane);
        float2 bv = __ldg((const float2*)Bv + lane);
        float lg = (d0 + av.x) * bv.x + (d1 + av.y) * bv.y;
        #pragma unroll
        for (int o = 16; o; o >>= 1) lg += __shfl_xor_sync(0xffffffffu, lg, o);
        if (lane == 0) out[ooff] = lg + bias;

        // reg1 += ||u1s||^2+||i1s||^2 (phase0,q0) ; reg2 += ||u2s||^2+||i2s||^2 (phase1,q1)
        if ((phase == 0 && q == 0) || (phase == 1 && q == 1))
            regacc += av.x * av.x + av.y * av.y + bv.x * bv.x + bv.y * bv.y;
    }

    // ---- block reduce reg loss, one atomic per block into out[4B + phase] ----
    #pragma unroll
    for (int o = 16; o; o >>= 1) regacc += __shfl_xor_sync(0xffffffffu, regacc, o);
    if (lane == 0) sred[warp] = regacc;
    __syncthreads();
    if (tid == 0)
        atomicAdd(out + 4 * B + phase, sred[0] + sred[1] + sred[2] + sred[3]);
}

extern "C" void kernel_launch(void* const* d_in, const int* in_sizes, int n_in,
                              void* d_out, int out_size) {
    const int B = in_sizes[0];
    float* out = (float*)d_out;

    zero_tail_kernel<<<1, 32>>>(out, 4 * B);
    fused_kernel<<<dim3(B, 2), NT>>>(
        (const int*)d_in[0], (const int*)d_in[1], (const int*)d_in[2], (const int*)d_in[3],
        (const int*)d_in[4], (const int*)d_in[5], (const int*)d_in[6],
        (const int*)d_in[7], (const int*)d_in[8], (const int*)d_in[9],
        (const float*)d_in[10], (const float*)d_in[11],
        (const float*)d_in[12], (const float*)d_in[13],
        (const float*)d_in[14],
        (const float*)d_in[15], (const float*)d_in[16],
        (const float*)d_in[17], (const float*)d_in[18],
        (const float*)d_in[19],
        (const float*)d_in[20], (const float*)d_in[21],
        (const float*)d_in[22], (const float*)d_in[23],
        out, B);
}